// round 1
// baseline (speedup 1.0000x reference)
#include <cuda_runtime.h>

#define MROWS  4096   // B*T
#define DMODEL 1024
#define T_SEQ  2048
#define NB     2
#define NH     16
#define DH     64

// Scratch (allocation-free rule: __device__ globals)
__device__ float g_Q[MROWS * DMODEL];
__device__ float g_K[MROWS * DMODEL];
__device__ float g_V[MROWS * DMODEL];
__device__ float g_Z[MROWS * DMODEL];

// ---------------------------------------------------------------------------
// GEMM: C[M,N] = A[M,K] * W[K,N], M=4096, N=K=1024, all row-major fp32.
// 64x64 block tile, BK=16, 256 threads, 4x4 register tile per thread.
// ---------------------------------------------------------------------------
__global__ __launch_bounds__(256) void gemm_k(const float* __restrict__ A,
                                              const float* __restrict__ W,
                                              float* __restrict__ C)
{
    __shared__ float As[16][65];   // [k][m], padded: conflict-free transposed store
    __shared__ float Ws[16][68];   // [k][n], padded to 16B-multiple rows for float4

    const int tid  = threadIdx.x;
    const int tx   = tid & 15;
    const int ty   = tid >> 4;
    const int row0 = blockIdx.y * 64;
    const int col0 = blockIdx.x * 64;

    // load-index decomposition
    const int la_row = tid >> 2;          // 0..63
    const int la_k   = (tid & 3) << 2;    // 0,4,8,12
    const int lw_k   = tid >> 4;          // 0..15
    const int lw_n   = (tid & 15) << 2;   // 0..60

    float acc[4][4];
#pragma unroll
    for (int i = 0; i < 4; i++)
#pragma unroll
        for (int j = 0; j < 4; j++) acc[i][j] = 0.f;

    for (int k0 = 0; k0 < DMODEL; k0 += 16) {
        float4 a4 = *(const float4*)&A[(row0 + la_row) * DMODEL + k0 + la_k];
        As[la_k + 0][la_row] = a4.x;
        As[la_k + 1][la_row] = a4.y;
        As[la_k + 2][la_row] = a4.z;
        As[la_k + 3][la_row] = a4.w;
        *(float4*)&Ws[lw_k][lw_n] =
            *(const float4*)&W[(k0 + lw_k) * DMODEL + col0 + lw_n];
        __syncthreads();

#pragma unroll
        for (int kk = 0; kk < 16; kk++) {
            float av[4];
#pragma unroll
            for (int i = 0; i < 4; i++) av[i] = As[kk][ty * 4 + i];
            float4 w4 = *(const float4*)&Ws[kk][tx * 4];
            float wv[4] = {w4.x, w4.y, w4.z, w4.w};
#pragma unroll
            for (int i = 0; i < 4; i++)
#pragma unroll
                for (int j = 0; j < 4; j++) acc[i][j] += av[i] * wv[j];
        }
        __syncthreads();
    }

#pragma unroll
    for (int i = 0; i < 4; i++) {
        float4 r = make_float4(acc[i][0], acc[i][1], acc[i][2], acc[i][3]);
        *(float4*)&C[(row0 + ty * 4 + i) * DMODEL + col0 + tx * 4] = r;
    }
}

// ---------------------------------------------------------------------------
// Causal flash attention, fp32. One thread owns one query row (q,o in regs).
// Block: 128 threads = 128 consecutive query rows of one (b,h).
// K/V tiles (64 keys x 64 dims) staged in smem; all compute reads are
// warp-uniform -> smem broadcast, conflict-free.
// ---------------------------------------------------------------------------
__global__ __launch_bounds__(128) void attn_k()
{
    __shared__ float Ks[64][64];
    __shared__ float Vs[64][64];

    const int tid  = threadIdx.x;
    const int bh   = blockIdx.y;
    const int b    = bh >> 4;
    const int h    = bh & 15;
    const int base = b * T_SEQ;                 // row offset of this sequence
    const int i    = blockIdx.x * 128 + tid;    // query position in sequence
    const int h64  = h * DH;
    const float scale = 0.125f;                 // 1/sqrt(64)

    float q[DH], o[DH];
    const float* qrow = &g_Q[(size_t)(base + i) * DMODEL + h64];
#pragma unroll
    for (int k = 0; k < DH; k += 4) {
        float4 v = *(const float4*)&qrow[k];
        q[k] = v.x; q[k + 1] = v.y; q[k + 2] = v.z; q[k + 3] = v.w;
    }
#pragma unroll
    for (int k = 0; k < DH; k++) o[k] = 0.f;
    float m = -1e30f, l = 0.f;

    const int ntiles = (blockIdx.x * 128 + 128) / 64;  // covers keys <= block max row
    for (int t = 0; t < ntiles; t++) {
        const int kt = t * 64;
        const float* Kg = &g_K[(size_t)(base + kt) * DMODEL + h64];
        const float* Vg = &g_V[(size_t)(base + kt) * DMODEL + h64];
#pragma unroll
        for (int c = 0; c < 8; c++) {
            int f  = tid + 128 * c;      // float4 slot 0..1023
            int j  = f >> 4;
            int k4 = (f & 15) << 2;
            *(float4*)&Ks[j][k4] = *(const float4*)&Kg[(size_t)j * DMODEL + k4];
            *(float4*)&Vs[j][k4] = *(const float4*)&Vg[(size_t)j * DMODEL + k4];
        }
        __syncthreads();

        if (i >= kt) {
#pragma unroll 1
            for (int j0 = 0; j0 < 64; j0 += 8) {
                if (kt + j0 > i) break;
                float s[8];
#pragma unroll
                for (int jj = 0; jj < 8; jj++) {
                    const float* kr = Ks[j0 + jj];
                    float a0 = 0.f, a1 = 0.f, a2 = 0.f, a3 = 0.f;
#pragma unroll
                    for (int k = 0; k < DH; k += 4) {
                        a0 += q[k]     * kr[k];
                        a1 += q[k + 1] * kr[k + 1];
                        a2 += q[k + 2] * kr[k + 2];
                        a3 += q[k + 3] * kr[k + 3];
                    }
                    float sv = (a0 + a1) + (a2 + a3);
                    s[jj] = sv * scale + ((kt + j0 + jj <= i) ? 0.f : -1e30f);
                }
                float cm = s[0];
#pragma unroll
                for (int jj = 1; jj < 8; jj++) cm = fmaxf(cm, s[jj]);
                if (cm > m) {                       // rescale only on new max
                    float corr = __expf(m - cm);
                    m = cm;
                    l *= corr;
#pragma unroll
                    for (int k = 0; k < DH; k++) o[k] *= corr;
                }
#pragma unroll
                for (int jj = 0; jj < 8; jj++) {
                    float p = __expf(s[jj] - m);    // masked -> exp(-huge)=0
                    l += p;
                    const float* vr = Vs[j0 + jj];
#pragma unroll
                    for (int k = 0; k < DH; k++) o[k] += p * vr[k];
                }
            }
        }
        __syncthreads();
    }

    const float inv = 1.f / l;
    float* zrow = &g_Z[(size_t)(base + i) * DMODEL + h64];
#pragma unroll
    for (int k = 0; k < DH; k += 4) {
        float4 v = make_float4(o[k] * inv, o[k + 1] * inv, o[k + 2] * inv, o[k + 3] * inv);
        *(float4*)&zrow[k] = v;
    }
}

// ---------------------------------------------------------------------------
extern "C" void kernel_launch(void* const* d_in, const int* in_sizes, int n_in,
                              void* d_out, int out_size)
{
    const float* x  = (const float*)d_in[0];
    const float* Wq = (const float*)d_in[1];
    const float* Wk = (const float*)d_in[2];
    const float* Wv = (const float*)d_in[3];
    const float* Wo = (const float*)d_in[4];
    float* out = (float*)d_out;

    float *Q, *K, *V, *Z;
    cudaGetSymbolAddress((void**)&Q, g_Q);
    cudaGetSymbolAddress((void**)&K, g_K);
    cudaGetSymbolAddress((void**)&V, g_V);
    cudaGetSymbolAddress((void**)&Z, g_Z);

    dim3 ggrid(DMODEL / 64, MROWS / 64);   // (16, 64)
    gemm_k<<<ggrid, 256>>>(x, Wq, Q);
    gemm_k<<<ggrid, 256>>>(x, Wk, K);
    gemm_k<<<ggrid, 256>>>(x, Wv, V);

    attn_k<<<dim3(T_SEQ / 128, NB * NH), 128>>>();

    gemm_k<<<ggrid, 256>>>(Z, Wo, out);
}